// round 5
// baseline (speedup 1.0000x reference)
#include <cuda_runtime.h>

// Hausdorff distance, batched N=8, grid 96x96, coords (i/96, j/96).
// haus[s] = max(directed(A\B -> B), directed(B\A -> A)), out = mean over s.
// float4 loads -> nibble masks -> packed 96-bit row masks;
// row-EDT via clz/ffs (divergence-free);
// source pixels compacted to a list, early-exit outward column scans spread
// over all 1024 threads.

#define HD 96
#define WD 96
#define HW (HD * WD)
#define NWORDS (HW / 32)      // 288 (= 9 warps)
#define NQUAD  (HW / 4)       // 2304
#define NT 1024

__device__ float        g_dir[64];
__device__ unsigned int g_count = 0;   // self-resetting last-block counter

static __device__ __forceinline__ unsigned pack_nib(unsigned x) {
    return (x & 0xFu) | ((x >> 4) & 0xF0u) | ((x >> 8) & 0xF00u) | ((x >> 12) & 0xF000u);
}

__global__ void __launch_bounds__(NT) hausdorff_kernel(
    const float* __restrict__ pred, const float* __restrict__ targ,
    float* __restrict__ out, int n) {
    __shared__ unsigned char  s_an[NQUAD];     // pred nibbles
    __shared__ unsigned char  s_bn[NQUAD];     // targ nibbles
    __shared__ unsigned int   s_am[NWORDS];    // pred row-mask words
    __shared__ unsigned int   s_bm[NWORDS];    // targ row-mask words
    __shared__ unsigned short s_rd2[HW];       // squared row distance (sentinel 40000)
    __shared__ unsigned short s_list[HW];      // compacted source pixel indices
    __shared__ int s_wtot[9];
    __shared__ int s_nsrc;
    __shared__ int s_red[32];

    const int s    = blockIdx.x;
    const int dir  = blockIdx.y;               // 0: tgt=B, src=A&~B ; 1: tgt=A, src=B&~A
    const int tid  = threadIdx.x;
    const int lane = tid & 31;
    const int wrp  = tid >> 5;

    const float4* __restrict__ P4 = (const float4*)(pred + s * HW);
    const float4* __restrict__ T4 = (const float4*)(targ + s * HW);

    // ---- Phase 1a: vectorized loads -> nibbles (round(x)>0.5 <=> x>0.5 on [0,1))
    for (int p = tid; p < NQUAD; p += NT) {
        float4 a = P4[p];
        float4 b = T4[p];
        unsigned na = (unsigned)(a.x > 0.5f) | ((unsigned)(a.y > 0.5f) << 1)
                    | ((unsigned)(a.z > 0.5f) << 2) | ((unsigned)(a.w > 0.5f) << 3);
        unsigned nb = (unsigned)(b.x > 0.5f) | ((unsigned)(b.y > 0.5f) << 1)
                    | ((unsigned)(b.z > 0.5f) << 2) | ((unsigned)(b.w > 0.5f) << 3);
        s_an[p] = (unsigned char)na;
        s_bn[p] = (unsigned char)nb;
    }
    __syncthreads();

    // ---- Phase 1b: pack 8 nibbles -> one mask word (288 threads)
    int myTgtNonzero = 0;
    unsigned srcw = 0;
    if (tid < NWORDS) {
        const unsigned* pa = (const unsigned*)s_an;
        const unsigned* pb = (const unsigned*)s_bn;
        unsigned am = pack_nib(pa[2 * tid]) | (pack_nib(pa[2 * tid + 1]) << 16);
        unsigned bm = pack_nib(pb[2 * tid]) | (pack_nib(pb[2 * tid + 1]) << 16);
        s_am[tid] = am;
        s_bm[tid] = bm;
        myTgtNonzero = (dir ? am : bm) != 0;
        srcw = dir ? (bm & ~am) : (am & ~bm);
    }
    const int anyTgt = __syncthreads_or(myTgtNonzero);

    // ---- Source-pixel compaction: warp scan of popcounts, then bit expansion
    int cnt = __popc(srcw);
    int inc = cnt;
    #pragma unroll
    for (int off = 1; off < 32; off <<= 1) {
        int t = __shfl_up_sync(0xffffffffu, inc, off);
        if (lane >= off) inc += t;
    }
    if (lane == 31 && wrp < 9) s_wtot[wrp] = inc;
    __syncthreads();
    if (tid == 0) {
        int a = 0;
        #pragma unroll
        for (int k = 0; k < 9; k++) { int t = s_wtot[k]; s_wtot[k] = a; a += t; }
        s_nsrc = a;
    }

    // ---- Phase 2 (overlapped before the sync): row distances squared.
    // Warp w (0..31) owns rows 3w..3w+2; lane handles j = lane, +32, +64.
    const unsigned int* __restrict__ st = dir ? s_am : s_bm;
    unsigned short rdv[3][3];
    #pragma unroll
    for (int rr = 0; rr < 3; rr++) {
        const int i = wrp * 3 + rr;
        const unsigned m0 = st[i * 3], m1 = st[i * 3 + 1], m2 = st[i * 3 + 2];
        const unsigned long long lo = (unsigned long long)m0 | ((unsigned long long)m1 << 32);
        const unsigned hi = m2;
        {   // j = lane
            const int j = lane;
            unsigned long long x = lo & (~0ULL >> (63 - j));
            int dl = x ? (j - (63 - __clzll(x))) : 200;
            unsigned long long y = lo >> j;
            int dr = y ? (__ffsll(y) - 1) : (hi ? (64 - j) + __ffs(hi) - 1 : 200);
            int v = min(dl, dr);
            rdv[rr][0] = (unsigned short)(v * v);
        }
        {   // j = lane+32
            const int j = lane + 32;
            unsigned long long x = lo & (~0ULL >> (63 - j));
            int dl = x ? (j - (63 - __clzll(x))) : 200;
            unsigned long long y = lo >> j;
            int dr = y ? (__ffsll(y) - 1) : (hi ? (64 - j) + __ffs(hi) - 1 : 200);
            int v = min(dl, dr);
            rdv[rr][1] = (unsigned short)(v * v);
        }
        {   // j = lane+64
            const int j = lane + 64;
            unsigned x = hi & (~0u >> (31 - lane));
            int dl;
            if (x)       dl = j - (64 + 31 - __clz(x));
            else if (lo) dl = j - (63 - __clzll(lo));
            else         dl = 200;
            unsigned y = hi >> lane;
            int dr = y ? (__ffs(y) - 1) : 200;
            int v = min(dl, dr);
            rdv[rr][2] = (unsigned short)(v * v);
        }
    }
    #pragma unroll
    for (int rr = 0; rr < 3; rr++) {
        const int i = wrp * 3 + rr;
        s_rd2[i * WD + lane]      = rdv[rr][0];
        s_rd2[i * WD + lane + 32] = rdv[rr][1];
        s_rd2[i * WD + lane + 64] = rdv[rr][2];
    }
    __syncthreads();

    // ---- Expand source bits into compacted list
    if (tid < NWORDS) {
        int ofs = s_wtot[wrp] + (inc - cnt);
        const int base = tid * 32;
        unsigned w = srcw;
        while (w) {
            int b = __ffs(w) - 1;
            w &= w - 1;
            s_list[ofs++] = (unsigned short)(base + b);
        }
    }
    __syncthreads();

    // ---- Phase 3: early-exit outward column scans, evenly over all threads
    const int nsrc = s_nsrc;
    int best = -1;
    for (int idx = tid; idx < nsrc; idx += NT) {
        const int p = s_list[idx];
        const int i = p / WD;
        const int j = p - i * WD;
        int bst = s_rd2[p];
        for (int di = 1; di <= 95 && di * di < bst; di++) {
            int d2 = di * di;
            int u = i - di, v = i + di;
            if (u >= 0) bst = min(bst, d2 + (int)s_rd2[u * WD + j]);
            if (v < HD) bst = min(bst, d2 + (int)s_rd2[v * WD + j]);
        }
        best = max(best, bst);
    }

    // ---- Block max-reduction
    #pragma unroll
    for (int off = 16; off > 0; off >>= 1)
        best = max(best, __shfl_xor_sync(0xffffffffu, best, off));
    if (lane == 0) s_red[wrp] = best;
    __syncthreads();
    if (tid == 0) {
        int m = s_red[0];
        #pragma unroll
        for (int k = 1; k < 32; k++) m = max(m, s_red[k]);
        float r;
        if (m < 0)        r = 0.0f;                      // empty source set
        else if (!anyTgt) r = 1e9f;                      // src nonempty, tgt empty
        else              r = sqrtf((float)m) * (1.0f / 96.0f);
        g_dir[s * 2 + dir] = r;
        __threadfence();
        unsigned int t = atomicAdd(&g_count, 1);
        if (t == (unsigned int)(2 * n - 1)) {            // last block: finish + reset
            __threadfence();
            volatile float* gd = g_dir;
            float acc = 0.0f;
            for (int i = 0; i < n; i++)
                acc += fmaxf(gd[2 * i], gd[2 * i + 1]);
            out[0] = acc / (float)n;
            g_count = 0;                                 // self-reset for next replay
        }
    }
}

extern "C" void kernel_launch(void* const* d_in, const int* in_sizes, int n_in,
                              void* d_out, int out_size) {
    const float* pred = (const float*)d_in[0];
    const float* targ = (const float*)d_in[1];
    float* out = (float*)d_out;
    int n = in_sizes[0] / HW;   // batch size (8)

    dim3 grid(n, 2);
    hausdorff_kernel<<<grid, NT>>>(pred, targ, out, n);
}

// round 6
// speedup vs baseline: 1.3810x; 1.3810x over previous
#include <cuda_runtime.h>

// Hausdorff distance, batched N=8, grid 96x96, coords (i/96, j/96).
// haus[s] = max(directed(A\B -> B), directed(B\A -> A)), out = mean over s.
// float4 loads -> nibble masks -> packed 96-bit row masks;
// row-EDT via clz/ffs; column scan with early exit, dense ownership:
// warp w owns rows 3w..3w+2, lane owns j = lane, lane+32, lane+64.

#define HD 96
#define WD 96
#define HW (HD * WD)
#define NWORDS (HW / 32)      // 288
#define NQUAD  (HW / 4)       // 2304
#define NT 1024

__device__ float        g_dir[64];
__device__ unsigned int g_count = 0;   // self-resetting last-block counter

static __device__ __forceinline__ unsigned pack_nib(unsigned x) {
    return (x & 0xFu) | ((x >> 4) & 0xF0u) | ((x >> 8) & 0xF00u) | ((x >> 12) & 0xF000u);
}

__global__ void __launch_bounds__(NT) hausdorff_kernel(
    const float* __restrict__ pred, const float* __restrict__ targ,
    float* __restrict__ out, int n) {
    __shared__ unsigned char  s_an[NQUAD];     // pred nibbles
    __shared__ unsigned char  s_bn[NQUAD];     // targ nibbles
    __shared__ unsigned int   s_tm[NWORDS];    // target row-mask words (per dir)
    __shared__ unsigned int   s_sw[NWORDS];    // source row-mask words (per dir)
    __shared__ unsigned short s_rd2[HW];       // squared row distance (sentinel 40000)
    __shared__ int s_red[32];

    const int s    = blockIdx.x;
    const int dir  = blockIdx.y;               // 0: tgt=B, src=A&~B ; 1: tgt=A, src=B&~A
    const int tid  = threadIdx.x;
    const int lane = tid & 31;
    const int wrp  = tid >> 5;                 // 0..31

    const float4* __restrict__ P4 = (const float4*)(pred + s * HW);
    const float4* __restrict__ T4 = (const float4*)(targ + s * HW);

    // ---- Phase 1a: vectorized loads -> nibbles (round(x)>0.5 <=> x>0.5 on [0,1))
    #pragma unroll
    for (int k = 0; k < 3; k++) {
        int p = tid + k * NT;
        if (p < NQUAD) {
            float4 a = P4[p];
            float4 b = T4[p];
            unsigned na = (unsigned)(a.x > 0.5f) | ((unsigned)(a.y > 0.5f) << 1)
                        | ((unsigned)(a.z > 0.5f) << 2) | ((unsigned)(a.w > 0.5f) << 3);
            unsigned nb = (unsigned)(b.x > 0.5f) | ((unsigned)(b.y > 0.5f) << 1)
                        | ((unsigned)(b.z > 0.5f) << 2) | ((unsigned)(b.w > 0.5f) << 3);
            s_an[p] = (unsigned char)na;
            s_bn[p] = (unsigned char)nb;
        }
    }
    __syncthreads();

    // ---- Phase 1b: pack 8 nibbles -> mask words; build target + source words
    int myTgtNonzero = 0;
    if (tid < NWORDS) {
        const unsigned* pa = (const unsigned*)s_an;
        const unsigned* pb = (const unsigned*)s_bn;
        unsigned am = pack_nib(pa[2 * tid]) | (pack_nib(pa[2 * tid + 1]) << 16);
        unsigned bm = pack_nib(pb[2 * tid]) | (pack_nib(pb[2 * tid + 1]) << 16);
        unsigned tm = dir ? am : bm;
        unsigned sw = dir ? (bm & ~am) : (am & ~bm);
        s_tm[tid] = tm;
        s_sw[tid] = sw;
        myTgtNonzero = (tm != 0);
    }
    const int anyTgt = __syncthreads_or(myTgtNonzero);

    // ---- Phase 2: squared row distances. Warp w owns rows 3w..3w+2;
    // lane handles j = lane, lane+32, lane+64 (branch-light, fixed ranges).
    #pragma unroll
    for (int rr = 0; rr < 3; rr++) {
        const int i = wrp * 3 + rr;
        const unsigned m0 = s_tm[i * 3], m1 = s_tm[i * 3 + 1], m2 = s_tm[i * 3 + 2];
        const unsigned long long lo = (unsigned long long)m0 | ((unsigned long long)m1 << 32);
        const unsigned hi = m2;
        int v0, v1, v2;
        {   // j = lane
            const int j = lane;
            unsigned long long x = lo & (~0ULL >> (63 - j));
            int dl = x ? (j - (63 - __clzll(x))) : 200;
            unsigned long long y = lo >> j;
            int dr = y ? (__ffsll(y) - 1) : (hi ? (64 - j) + __ffs(hi) - 1 : 200);
            v0 = min(dl, dr);
        }
        {   // j = lane+32
            const int j = lane + 32;
            unsigned long long x = lo & (~0ULL >> (63 - j));
            int dl = x ? (j - (63 - __clzll(x))) : 200;
            unsigned long long y = lo >> j;
            int dr = y ? (__ffsll(y) - 1) : (hi ? (64 - j) + __ffs(hi) - 1 : 200);
            v1 = min(dl, dr);
        }
        {   // j = lane+64
            const int j = lane + 64;
            unsigned x = hi & (~0u >> (31 - lane));
            int dl;
            if (x)       dl = j - (64 + 31 - __clz(x));
            else if (lo) dl = j - (63 - __clzll(lo));
            else         dl = 200;
            unsigned y = hi >> lane;
            int dr = y ? (__ffs(y) - 1) : 200;
            v2 = min(dl, dr);
        }
        s_rd2[i * WD + lane]      = (unsigned short)(v0 * v0);
        s_rd2[i * WD + lane + 32] = (unsigned short)(v1 * v1);
        s_rd2[i * WD + lane + 64] = (unsigned short)(v2 * v2);
    }
    __syncthreads();

    // ---- Phase 3: early-exit outward column scan, dense ownership (9 px/thread).
    // Non-source pixels get bst=-1 => zero scan iterations, preserved by max().
    int best = -1;
    #pragma unroll
    for (int rr = 0; rr < 3; rr++) {
        const int i = wrp * 3 + rr;
        const int rowbase = i * WD;
        #pragma unroll
        for (int c = 0; c < 3; c++) {
            const int j = lane + 32 * c;
            const unsigned sw = s_sw[i * 3 + c];         // warp-uniform broadcast
            int bst = ((sw >> lane) & 1u) ? (int)s_rd2[rowbase + j] : -1;
            for (int di = 1; di * di < bst; di++) {
                int d2 = di * di;
                int u = i - di, v = i + di;
                if (u >= 0) bst = min(bst, d2 + (int)s_rd2[u * WD + j]);
                if (v < HD) bst = min(bst, d2 + (int)s_rd2[v * WD + j]);
            }
            best = max(best, bst);
        }
    }

    // ---- Block max-reduction
    #pragma unroll
    for (int off = 16; off > 0; off >>= 1)
        best = max(best, __shfl_xor_sync(0xffffffffu, best, off));
    if (lane == 0) s_red[wrp] = best;
    __syncthreads();
    if (tid == 0) {
        int m = s_red[0];
        #pragma unroll
        for (int k = 1; k < 32; k++) m = max(m, s_red[k]);
        float r;
        if (m < 0)        r = 0.0f;                      // empty source set
        else if (!anyTgt) r = 1e9f;                      // src nonempty, tgt empty
        else              r = sqrtf((float)m) * (1.0f / 96.0f);
        g_dir[s * 2 + dir] = r;
        __threadfence();
        unsigned int t = atomicAdd(&g_count, 1);
        if (t == (unsigned int)(2 * n - 1)) {            // last block: finish + reset
            __threadfence();
            volatile float* gd = g_dir;
            float acc = 0.0f;
            for (int i = 0; i < n; i++)
                acc += fmaxf(gd[2 * i], gd[2 * i + 1]);
            out[0] = acc / (float)n;
            g_count = 0;                                 // self-reset for next replay
        }
    }
}

extern "C" void kernel_launch(void* const* d_in, const int* in_sizes, int n_in,
                              void* d_out, int out_size) {
    const float* pred = (const float*)d_in[0];
    const float* targ = (const float*)d_in[1];
    float* out = (float*)d_out;
    int n = in_sizes[0] / HW;   // batch size (8)

    dim3 grid(n, 2);
    hausdorff_kernel<<<grid, NT>>>(pred, targ, out, n);
}